// round 4
// baseline (speedup 1.0000x reference)
#include <cuda_runtime.h>

#define DD 128
#define GG 384
#define BV 256
#define MM 32
#define LL 24
#define NOUT 193

typedef unsigned long long u64;

// ---------------- scratch (static device globals; no allocation) -------------
__device__ float g_e3[3 * BV * DD];            // cond/proc/drug visit embeddings
__device__ float g_mon[2 * BV * MM * DD];      // lab / inj monitor embeddings
__device__ float g_xg34[2 * BV * MM * GG];     // monitor input-gates keys 3,4: [pair][grp32][t][3][s8][d128]
__device__ float g_xg012[3 * BV * GG];         // monitor input-gates keys 0-2: [key][grp32][3][s8][d128]
__device__ float g_h5[5 * BV * DD];            // monitor final hidden
__device__ float g_vxg[7 * 16 * 16 * GG];      // visit input-gates
__device__ float g_hv[7 * 16 * DD];            // visit final hidden
__device__ float g_wT[24 * DD * GG];           // transposed weights [d][g]

#define WIH_M 0
#define WHH_M (5 * DD * GG)
#define WIH_V (10 * DD * GG)
#define WHH_V (17 * DD * GG)

__device__ __forceinline__ float sigf(float x) { return 1.0f / (1.0f + __expf(-x)); }

// f32x2 packed helpers (Blackwell)
__device__ __forceinline__ u64 pack2(float x) {
    u64 r; asm("mov.b64 %0, {%1, %1};" : "=l"(r) : "f"(x)); return r;
}
__device__ __forceinline__ void ffma2(u64& acc, u64 a, u64 b) {
    asm("fma.rn.f32x2 %0, %1, %2, %0;" : "+l"(acc) : "l"(a), "l"(b));
}
__device__ __forceinline__ void unpack2(u64 a, float& lo, float& hi) {
    asm("mov.b64 {%0, %1}, %2;" : "=f"(lo), "=f"(hi) : "l"(a));
}

// ---------------- K0: transpose all GRU weights to [d][g] --------------------
__global__ void k_transpose(const float* mih, const float* mhh,
                            const float* vih, const float* vhh) {
    int y = blockIdx.y;      // 0..23: which (tensor,key)
    int g = blockIdx.x;      // 0..383
    int d = threadIdx.x;     // 0..127
    const float* src; int k;
    if (y < 5)       { src = mih; k = y; }
    else if (y < 10) { src = mhh; k = y - 5; }
    else if (y < 17) { src = vih; k = y - 10; }
    else             { src = vhh; k = y - 17; }
    g_wT[y * (DD * GG) + d * GG + g] = src[(k * GG + g) * DD + d];
}

// ---------------- K1: visit-event embedding sums ------------------------------
__global__ void k_embed_visit(const int* tc, const int* tp, const int* td,
                              const float* ec, const float* ep, const float* ed) {
    int n = blockIdx.x, key = blockIdx.y, d = threadIdx.x;
    const int* tok = (key == 0) ? tc : (key == 1) ? tp : td;
    const float* emb = (key == 0) ? ec : (key == 1) ? ep : ed;
    float acc = 0.f;
#pragma unroll
    for (int l = 0; l < LL; l++) acc += emb[tok[n * LL + l] * DD + d];
    g_e3[(key * BV + n) * DD + d] = acc;
}

// ---------------- K2: monitor-event pair embedding sums (float4) -------------
__global__ void k_embed_mon(const int* __restrict__ tli, const int* __restrict__ tlv,
                            const int* __restrict__ tii, const int* __restrict__ tiv,
                            const float* __restrict__ eli, const float* __restrict__ elv,
                            const float* __restrict__ eii, const float* __restrict__ eiv) {
    int pair = blockIdx.y;
    int r = blockIdx.x * 4 + (threadIdx.x >> 5);   // monitor row 0..8191
    int lane = threadIdx.x & 31;
    const int* ti = pair ? tii : tli;
    const int* tv = pair ? tiv : tlv;
    const float4* ei = (const float4*)(pair ? eii : eli);
    const float4* ev = (const float4*)(pair ? eiv : elv);
    float4 acc = make_float4(0.f, 0.f, 0.f, 0.f);
#pragma unroll
    for (int l = 0; l < LL; l++) {
        int a = ti[r * LL + l];
        int b = tv[r * LL + l];
        float4 x = ei[a * 32 + lane];
        float4 y = ev[b * 32 + lane];
        acc.x += x.x * y.x; acc.y += x.y * y.y;
        acc.z += x.z * y.z; acc.w += x.w * y.w;
    }
    ((float4*)g_mon)[(pair * 8192 + r) * 32 + lane] = acc;
}

// ---------------- K3a: monitor input-gates keys 3,4 — W in SMEM, 2 seq/CTA ----
// grid (128, 2), block 384, dyn smem = (DD*GG + 2*MM*DD)*4 = 229376 B
__global__ void __launch_bounds__(384) k_xg34(const float* bih) {
    extern __shared__ float sm[];
    float* s_w = sm;              // [128][384]
    float* s_x = sm + DD * GG;    // [2][128][32] (x transposed, 128B rows)
    int pair = blockIdx.y, bx = blockIdx.x;
    int n0 = bx * 2, key = 3 + pair, g = threadIdx.x;
    for (int i = g; i < DD * GG; i += GG) s_w[i] = g_wT[WIH_M + key * (DD * GG) + i];
    for (int i = g; i < 2 * MM * DD; i += GG) {
        int n = i >> 12, t = (i >> 7) & 31, d = i & 127;
        s_x[n * 4096 + d * 32 + t] = g_mon[((pair * BV + n0 + n) * MM + t) * DD + d];
    }
    __syncthreads();
    u64 b2 = pack2(bih[key * GG + g]);
    u64 accA[16], accB[16];
#pragma unroll
    for (int q = 0; q < 16; q++) { accA[q] = b2; accB[q] = b2; }
#pragma unroll 2
    for (int d = 0; d < DD; d++) {
        u64 w2 = pack2(s_w[d * GG + g]);
        const ulonglong2* xa = (const ulonglong2*)(s_x + d * 32);
        const ulonglong2* xb = (const ulonglong2*)(s_x + 4096 + d * 32);
#pragma unroll
        for (int q = 0; q < 8; q++) {
            ulonglong2 A = xa[q];
            ffma2(accA[2 * q], w2, A.x); ffma2(accA[2 * q + 1], w2, A.y);
        }
#pragma unroll
        for (int q = 0; q < 8; q++) {
            ulonglong2 B = xb[q];
            ffma2(accB[2 * q], w2, B.x); ffma2(accB[2 * q + 1], w2, B.y);
        }
    }
    // store: [pair][grp32][t][3][s8][d128], coalesced over d
    int gate = g >> 7, gd = g & 127;
#pragma unroll
    for (int n = 0; n < 2; n++) {
        int nn = n0 + n;
        int grp = nn >> 3, s = nn & 7;
        float* out = &g_xg34[(((((pair * 32 + grp) * MM) * 3 + gate) * 8 + s) * 128) + gd];
        u64* acc = n ? accB : accA;
#pragma unroll
        for (int q = 0; q < 16; q++) {
            float lo, hi; unpack2(acc[q], lo, hi);
            out[(2 * q) * (3 * 8 * 128)] = lo;
            out[(2 * q + 1) * (3 * 8 * 128)] = hi;
        }
    }
}

// ---------------- K3b: monitor input-gates keys 0-2 (t-invariant) -------------
__global__ void k_xg012(const float* bih) {
    __shared__ float sx[DD];
    int key = blockIdx.y, n = blockIdx.x, g = threadIdx.x;
    if (g < DD) sx[g] = g_e3[(key * BV + n) * DD + g];
    __syncthreads();
    float acc = bih[key * GG + g];
    const float* w = &g_wT[WIH_M + key * (DD * GG) + g];
#pragma unroll 4
    for (int d = 0; d < DD; d++) acc += w[d * GG] * sx[d];
    // store: [key][grp32][3][s8][d128]
    g_xg012[(((key * 32 + (n >> 3)) * 3 + (g >> 7)) * 8 + (n & 7)) * 128 + (g & 127)] = acc;
}

// ---------------- K4: monitor GRU recurrence — hT [d][8], FFMA2 ----------------
// grid (32, 5), block 384, dyn smem = (DD*GG + DD*8 + 8*GG)*4 = 212992 B
__global__ void __launch_bounds__(384) k_mon_gru(const float* bhh) {
    extern __shared__ float sm[];
    float* s_w = sm;                 // [128][384]
    float* s_hT = sm + DD * GG;      // [128][8]  32B rows
    float* s_gh = s_hT + DD * 8;     // [8][384]
    int key = blockIdx.y, grp = blockIdx.x, g = threadIdx.x;
    int n0 = grp * 8;
    for (int i = g; i < DD * GG; i += GG) s_w[i] = g_wT[WHH_M + key * (DD * GG) + i];
    for (int i = g; i < DD * 8; i += GG) s_hT[i] = 0.f;
    __syncthreads();
    u64 b2 = pack2(bhh[key * GG + g]);
    int gs = g >> 7, gd = g & 127;
    const float* xg_base;
    int xg_tstride;
    if (key < 3) {
        xg_base = &g_xg012[((key * 32 + grp) * 3) * (8 * 128)];
        xg_tstride = 0;
    } else {
        xg_base = &g_xg34[(((key - 3) * 32 + grp) * MM) * (3 * 8 * 128)];
        xg_tstride = 3 * 8 * 128;
    }
    for (int t = 0; t < MM; t++) {
        u64 a0 = b2, a1 = b2, a2 = b2, a3 = b2;
#pragma unroll 4
        for (int d = 0; d < DD; d++) {
            u64 w2 = pack2(s_w[d * GG + g]);
            const ulonglong2* h4 = (const ulonglong2*)(s_hT + d * 8);
            ulonglong2 hA = h4[0];
            ulonglong2 hB = h4[1];
            ffma2(a0, w2, hA.x); ffma2(a1, w2, hA.y);
            ffma2(a2, w2, hB.x); ffma2(a3, w2, hB.y);
        }
        float lo, hi;
        unpack2(a0, lo, hi); s_gh[0 * GG + g] = lo; s_gh[1 * GG + g] = hi;
        unpack2(a1, lo, hi); s_gh[2 * GG + g] = lo; s_gh[3 * GG + g] = hi;
        unpack2(a2, lo, hi); s_gh[4 * GG + g] = lo; s_gh[5 * GG + g] = hi;
        unpack2(a3, lo, hi); s_gh[6 * GG + g] = lo; s_gh[7 * GG + g] = hi;
        __syncthreads();
        const float* xg_t = xg_base + t * xg_tstride;
#pragma unroll
        for (int p = 0; p < 3; p++) {
            int s = gs + p * 3;
            if (s < 8) {
                float xr = xg_t[0 * 1024 + s * 128 + gd];
                float xz = xg_t[1 * 1024 + s * 128 + gd];
                float xn = xg_t[2 * 1024 + s * 128 + gd];
                float ghr = s_gh[s * GG + gd];
                float ghz = s_gh[s * GG + DD + gd];
                float ghn = s_gh[s * GG + 2 * DD + gd];
                float h = s_hT[gd * 8 + s];
                float r = sigf(xr + ghr);
                float z = sigf(xz + ghz);
                float nn = tanhf(xn + r * ghn);
                s_hT[gd * 8 + s] = (1.f - z) * nn + z * h;
            }
        }
        __syncthreads();
    }
    for (int i = g; i < 8 * DD; i += GG) {
        int s = i >> 7, d = i & 127;
        g_h5[(key * BV + n0 + s) * DD + d] = s_hT[d * 8 + s];
    }
}

// ---------------- K5: visit input-gates (plain fp32, R2 version) ---------------
__global__ void __launch_bounds__(384) k_vxg(const float* weight, const float* age,
                                             const float* info_w, const float* info_b,
                                             const float* bih) {
    __shared__ float sx[16 * DD];
    int key = blockIdx.y, b = blockIdx.x, g = threadIdx.x;
    for (int i = g; i < 16 * DD; i += GG) {
        int v = i / DD, d = i % DD;
        float x;
        if (key < 5)       x = g_h5[(key * BV + b * 16 + v) * DD + d];
        else if (key == 5) x = weight[b * 16 + v] * info_w[d] + info_b[d];
        else               x = age[b * 16 + v] * info_w[DD + d] + info_b[DD + d];
        sx[i] = x;
    }
    __syncthreads();
    float bb = bih[key * GG + g];
    float acc[16];
#pragma unroll
    for (int v = 0; v < 16; v++) acc[v] = bb;
    const float* w = &g_wT[WIH_V + key * (DD * GG) + g];
    for (int d = 0; d < DD; d++) {
        float wv = w[d * GG];
#pragma unroll
        for (int v = 0; v < 16; v++) acc[v] += wv * sx[v * DD + d];
    }
    float* out = &g_vxg[((key * 16 + b) * 16) * GG + g];
#pragma unroll
    for (int v = 0; v < 16; v++) out[v * GG] = acc[v];
}

// ---------------- K6: visit GRU recurrence --------------------------------------
// grid (16, 7), block 384, dyn smem = (DD*GG + DD + GG)*4 = 198656 B
__global__ void __launch_bounds__(384) k_vis_gru(const float* bhh) {
    extern __shared__ float sm[];
    float* s_w = sm;
    float* s_h = sm + DD * GG;
    float* s_gh = s_h + DD;
    int key = blockIdx.y, b = blockIdx.x, g = threadIdx.x;
    for (int i = g; i < DD * GG; i += GG) s_w[i] = g_wT[WHH_V + key * (DD * GG) + i];
    if (g < DD) s_h[g] = 0.f;
    __syncthreads();
    float bb = bhh[key * GG + g];
    for (int t = 0; t < 16; t++) {
        float acc = bb;
#pragma unroll 4
        for (int d = 0; d < DD; d++) acc += s_w[d * GG + g] * s_h[d];
        s_gh[g] = acc;
        __syncthreads();
        if (g < DD) {
            const float* xg = &g_vxg[((key * 16 + b) * 16 + t) * GG];
            float r = sigf(xg[g] + s_gh[g]);
            float z = sigf(xg[DD + g] + s_gh[DD + g]);
            float nn = tanhf(xg[2 * DD + g] + r * s_gh[2 * DD + g]);
            s_h[g] = (1.f - z) * nn + z * s_h[g];
        }
        __syncthreads();
    }
    if (g < DD) g_hv[(key * 16 + b) * DD + g] = s_h[g];
}

// ---------------- K7: ReLU + final FC --------------------------------------------
__global__ void k_fc(const float* fcw, const float* fcb, float* out) {
    __shared__ float pe[7 * DD];
    int b = blockIdx.x, o = threadIdx.x;
    for (int i = o; i < 7 * DD; i += 256) {
        int k = i / DD, d = i % DD;
        pe[i] = fmaxf(g_hv[(k * 16 + b) * DD + d], 0.f);
    }
    __syncthreads();
    if (o < NOUT) {
        float acc = fcb[o];
        for (int j = 0; j < 7 * DD; j++) acc += pe[j] * fcw[j * NOUT + o];
        out[b * NOUT + o] = acc;
    }
}

// ---------------- launch -----------------------------------------------------------
extern "C" void kernel_launch(void* const* d_in, const int* in_sizes, int n_in,
                              void* d_out, int out_size) {
    const int* tok_cond      = (const int*)d_in[0];
    const int* tok_proc      = (const int*)d_in[1];
    const int* tok_drug      = (const int*)d_in[2];
    const int* tok_lab_item  = (const int*)d_in[3];
    const int* tok_lab_value = (const int*)d_in[4];
    const int* tok_inj_item  = (const int*)d_in[5];
    const int* tok_inj_value = (const int*)d_in[6];
    const float* weight      = (const float*)d_in[7];
    const float* age         = (const float*)d_in[8];
    const float* emb_cond    = (const float*)d_in[9];
    const float* emb_proc    = (const float*)d_in[10];
    const float* emb_drug    = (const float*)d_in[11];
    const float* emb_li      = (const float*)d_in[12];
    const float* emb_lv      = (const float*)d_in[13];
    const float* emb_ii      = (const float*)d_in[14];
    const float* emb_iv      = (const float*)d_in[15];
    const float* mgru_wih    = (const float*)d_in[16];
    const float* mgru_whh    = (const float*)d_in[17];
    const float* mgru_bih    = (const float*)d_in[18];
    const float* mgru_bhh    = (const float*)d_in[19];
    const float* vgru_wih    = (const float*)d_in[20];
    const float* vgru_whh    = (const float*)d_in[21];
    const float* vgru_bih    = (const float*)d_in[22];
    const float* vgru_bhh    = (const float*)d_in[23];
    const float* info_w      = (const float*)d_in[24];
    const float* info_b      = (const float*)d_in[25];
    const float* fc_w        = (const float*)d_in[26];
    const float* fc_b        = (const float*)d_in[27];
    float* out = (float*)d_out;

    cudaFuncSetAttribute(k_xg34,    cudaFuncAttributeMaxDynamicSharedMemorySize, 229376);
    cudaFuncSetAttribute(k_mon_gru, cudaFuncAttributeMaxDynamicSharedMemorySize, 212992);
    cudaFuncSetAttribute(k_vis_gru, cudaFuncAttributeMaxDynamicSharedMemorySize, 198656);

    k_transpose<<<dim3(384, 24), 128>>>(mgru_wih, mgru_whh, vgru_wih, vgru_whh);
    k_embed_visit<<<dim3(256, 3), 128>>>(tok_cond, tok_proc, tok_drug,
                                         emb_cond, emb_proc, emb_drug);
    k_embed_mon<<<dim3(2048, 2), 128>>>(tok_lab_item, tok_lab_value,
                                        tok_inj_item, tok_inj_value,
                                        emb_li, emb_lv, emb_ii, emb_iv);
    k_xg34<<<dim3(128, 2), 384, 229376>>>(mgru_bih);
    k_xg012<<<dim3(256, 3), 384>>>(mgru_bih);
    k_mon_gru<<<dim3(32, 5), 384, 212992>>>(mgru_bhh);
    k_vxg<<<dim3(16, 7), 384>>>(weight, age, info_w, info_b, vgru_bih);
    k_vis_gru<<<dim3(16, 7), 384, 198656>>>(vgru_bhh);
    k_fc<<<16, 256>>>(fc_w, fc_b, out);
}

// round 5
// speedup vs baseline: 1.2486x; 1.2486x over previous
#include <cuda_runtime.h>

#define DD 128
#define GG 384
#define BV 256
#define MM 32
#define LL 24
#define NOUT 193
#define NSEQ 9
#define WPAD 132

typedef unsigned long long u64;

// ---------------- scratch (static device globals; no allocation) -------------
__device__ float g_e3[3 * BV * DD];            // cond/proc/drug visit embeddings
__device__ float g_mon[2 * BV * MM * DD];      // lab / inj monitor embeddings
__device__ float g_xg34[2 * BV * MM * GG];     // monitor input-gates, keys 3,4
__device__ float g_xg012[3 * BV * GG];         // monitor input-gates, keys 0-2 (t-invariant)
__device__ float g_h5[5 * BV * DD];            // monitor final hidden
__device__ float g_vxg[7 * 16 * 16 * GG];      // visit input-gates
__device__ float g_hv[7 * 16 * DD];            // visit final hidden
__device__ float g_wT[24 * DD * GG];           // transposed weights [d][g]

#define WIH_M 0
#define WHH_M (5 * DD * GG)
#define WIH_V (10 * DD * GG)
#define WHH_V (17 * DD * GG)

__device__ __forceinline__ float sigf(float x) { return 1.0f / (1.0f + __expf(-x)); }

// f32x2 packed helpers (Blackwell)
__device__ __forceinline__ u64 pack_lo(float x) {
    u64 r; asm("mov.b64 %0, {%1, %2};" : "=l"(r) : "f"(x), "f"(0.0f)); return r;
}
__device__ __forceinline__ void ffma2(u64& acc, u64 a, u64 b) {
    asm("fma.rn.f32x2 %0, %1, %2, %0;" : "+l"(acc) : "l"(a), "l"(b));
}
__device__ __forceinline__ float hsum2(u64 a) {
    float lo, hi; asm("mov.b64 {%0, %1}, %2;" : "=f"(lo), "=f"(hi) : "l"(a));
    return lo + hi;
}

// ---------------- K0: transpose all GRU weights to [d][g] --------------------
__global__ void k_transpose(const float* mih, const float* mhh,
                            const float* vih, const float* vhh) {
    int y = blockIdx.y;      // 0..23: which (tensor,key)
    int g = blockIdx.x;      // 0..383
    int d = threadIdx.x;     // 0..127
    const float* src; int k;
    if (y < 5)       { src = mih; k = y; }
    else if (y < 10) { src = mhh; k = y - 5; }
    else if (y < 17) { src = vih; k = y - 10; }
    else             { src = vhh; k = y - 17; }
    g_wT[y * (DD * GG) + d * GG + g] = src[(k * GG + g) * DD + d];
}

// ---------------- K1: visit-event embedding sums ------------------------------
__global__ void k_embed_visit(const int* tc, const int* tp, const int* td,
                              const float* ec, const float* ep, const float* ed) {
    int n = blockIdx.x, key = blockIdx.y, d = threadIdx.x;
    const int* tok = (key == 0) ? tc : (key == 1) ? tp : td;
    const float* emb = (key == 0) ? ec : (key == 1) ? ep : ed;
    float acc = 0.f;
#pragma unroll
    for (int l = 0; l < LL; l++) acc += emb[tok[n * LL + l] * DD + d];
    g_e3[(key * BV + n) * DD + d] = acc;
}

// ---------------- K2: monitor-event pair embedding sums (float4) -------------
__global__ void k_embed_mon(const int* __restrict__ tli, const int* __restrict__ tlv,
                            const int* __restrict__ tii, const int* __restrict__ tiv,
                            const float* __restrict__ eli, const float* __restrict__ elv,
                            const float* __restrict__ eii, const float* __restrict__ eiv) {
    int pair = blockIdx.y;
    int r = blockIdx.x * 4 + (threadIdx.x >> 5);   // monitor row 0..8191
    int lane = threadIdx.x & 31;
    const int* ti = pair ? tii : tli;
    const int* tv = pair ? tiv : tlv;
    const float4* ei = (const float4*)(pair ? eii : eli);
    const float4* ev = (const float4*)(pair ? eiv : elv);
    float4 acc = make_float4(0.f, 0.f, 0.f, 0.f);
#pragma unroll
    for (int l = 0; l < LL; l++) {
        int a = ti[r * LL + l];
        int b = tv[r * LL + l];
        float4 x = ei[a * 32 + lane];
        float4 y = ev[b * 32 + lane];
        acc.x += x.x * y.x; acc.y += x.y * y.y;
        acc.z += x.z * y.z; acc.w += x.w * y.w;
    }
    ((float4*)g_mon)[(pair * 8192 + r) * 32 + lane] = acc;
}

// ---------------- K3a: monitor input-gates for keys 3,4 (R2 version) ----------
__global__ void __launch_bounds__(384) k_xg34(const float* bih) {
    __shared__ float sx[DD * 36];   // x transposed [d][t], pad 4 (16B-aligned rows)
    int pair = blockIdx.y, n = blockIdx.x, key = 3 + pair;
    int g = threadIdx.x;
    for (int i = g; i < MM * DD; i += GG) {
        int t = i / DD, d = i % DD;
        sx[d * 36 + t] = g_mon[((pair * BV + n) * MM + t) * DD + d];
    }
    __syncthreads();
    float b = bih[key * GG + g];
    float acc[MM];
#pragma unroll
    for (int t = 0; t < MM; t++) acc[t] = b;
    const float* w = &g_wT[WIH_M + key * (DD * GG) + g];
    for (int d = 0; d < DD; d++) {
        float wv = w[d * GG];
        const float4* x4 = (const float4*)&sx[d * 36];
#pragma unroll
        for (int q = 0; q < 8; q++) {
            float4 x = x4[q];
            acc[q * 4 + 0] += wv * x.x; acc[q * 4 + 1] += wv * x.y;
            acc[q * 4 + 2] += wv * x.z; acc[q * 4 + 3] += wv * x.w;
        }
    }
    float* out = &g_xg34[((pair * BV + n) * MM) * GG + g];
#pragma unroll
    for (int t = 0; t < MM; t++) out[t * GG] = acc[t];
}

// ---------------- K3b: monitor input-gates for keys 0-2 (t-invariant) --------
__global__ void k_xg012(const float* bih) {
    __shared__ float sx[DD];
    int key = blockIdx.y, n = blockIdx.x, g = threadIdx.x;
    if (g < DD) sx[g] = g_e3[(key * BV + n) * DD + g];
    __syncthreads();
    float acc = bih[key * GG + g];
    const float* w = &g_wT[WIH_M + key * (DD * GG) + g];
#pragma unroll 4
    for (int d = 0; d < DD; d++) acc += w[d * GG] * sx[d];
    g_xg012[(key * BV + n) * GG + g] = acc;
}

// ---------------- K4: monitor GRU recurrence — W [g][d] pad132, FFMA2 ---------
// grid (29, 5), block 384, dyn smem = (GG*WPAD + NSEQ*DD + NSEQ*GG)*4 = 221184 B
__global__ void __launch_bounds__(384) k_mon_gru(const float* __restrict__ whh,
                                                 const float* __restrict__ bhh) {
    extern __shared__ float sm[];
    float* s_w = sm;                       // [384][132]  202752 B
    float* s_h = sm + GG * WPAD;           // [9][128]      4608 B
    float* s_gh = s_h + NSEQ * DD;         // [9][384]     13824 B
    int key = blockIdx.y, grp = blockIdx.x, g = threadIdx.x;
    int n0 = grp * NSEQ;
    int ns = min(NSEQ, BV - n0);
    // whh is already [g][d] row-major per key; coalesced copy into padded rows
    for (int i = g; i < GG * DD; i += GG) {
        int row = i >> 7, col = i & 127;
        s_w[row * WPAD + col] = whh[key * (GG * DD) + i];
    }
    for (int i = g; i < NSEQ * DD; i += GG) s_h[i] = 0.f;
    __syncthreads();
    float bb = bhh[key * GG + g];
    int ss = g >> 7, dd = g & 127;
    const ulonglong2* wrow = (const ulonglong2*)(s_w + g * WPAD);
    for (int t = 0; t < MM; t++) {
        u64 acc[NSEQ];
#pragma unroll
        for (int s = 0; s < NSEQ; s++) acc[s] = pack_lo(s == 0 ? bb : 0.0f);
#pragma unroll 4
        for (int dc = 0; dc < 32; dc++) {
            ulonglong2 w4 = wrow[dc];
#pragma unroll
            for (int s = 0; s < NSEQ; s++) {
                ulonglong2 h4 = *(const ulonglong2*)(s_h + s * DD + dc * 4);
                ffma2(acc[s], w4.x, h4.x);
                ffma2(acc[s], w4.y, h4.y);
            }
        }
        {
            float g0 = hsum2(acc[0]);            // includes bias
            s_gh[0 * GG + g] = g0;
#pragma unroll
            for (int s = 1; s < NSEQ; s++) s_gh[s * GG + g] = bb + hsum2(acc[s]);
        }
        __syncthreads();
#pragma unroll
        for (int sb = 0; sb < NSEQ; sb += 3) {
            int s = sb + ss;
            if (s < ns) {
                int n = n0 + s;
                const float* xg = (key < 3)
                    ? &g_xg012[(key * BV + n) * GG]
                    : &g_xg34[(((key - 3) * BV + n) * MM + t) * GG];
                float ghr = s_gh[s * GG + dd];
                float ghz = s_gh[s * GG + DD + dd];
                float ghn = s_gh[s * GG + 2 * DD + dd];
                float h = s_h[s * DD + dd];
                float r = sigf(xg[dd] + ghr);
                float z = sigf(xg[DD + dd] + ghz);
                float nn = tanhf(xg[2 * DD + dd] + r * ghn);
                s_h[s * DD + dd] = (1.f - z) * nn + z * h;
            }
        }
        __syncthreads();
    }
    for (int i = g; i < ns * DD; i += GG) g_h5[(key * BV + n0) * DD + i] = s_h[i];
}

// ---------------- K5: visit input-gates (R2 version) ---------------------------
__global__ void __launch_bounds__(384) k_vxg(const float* weight, const float* age,
                                             const float* info_w, const float* info_b,
                                             const float* bih) {
    __shared__ float sx[16 * DD];
    int key = blockIdx.y, b = blockIdx.x, g = threadIdx.x;
    for (int i = g; i < 16 * DD; i += GG) {
        int v = i / DD, d = i % DD;
        float x;
        if (key < 5)       x = g_h5[(key * BV + b * 16 + v) * DD + d];
        else if (key == 5) x = weight[b * 16 + v] * info_w[d] + info_b[d];
        else               x = age[b * 16 + v] * info_w[DD + d] + info_b[DD + d];
        sx[i] = x;
    }
    __syncthreads();
    float bb = bih[key * GG + g];
    float acc[16];
#pragma unroll
    for (int v = 0; v < 16; v++) acc[v] = bb;
    const float* w = &g_wT[WIH_V + key * (DD * GG) + g];
    for (int d = 0; d < DD; d++) {
        float wv = w[d * GG];
#pragma unroll
        for (int v = 0; v < 16; v++) acc[v] += wv * sx[v * DD + d];
    }
    float* out = &g_vxg[((key * 16 + b) * 16) * GG + g];
#pragma unroll
    for (int v = 0; v < 16; v++) out[v * GG] = acc[v];
}

// ---------------- K6: visit GRU recurrence -------------------------------------
// grid (16, 7), block 384, dyn smem = (DD*GG + DD + GG)*4 = 198656 B
__global__ void __launch_bounds__(384) k_vis_gru(const float* bhh) {
    extern __shared__ float sm[];
    float* s_w = sm;
    float* s_h = sm + DD * GG;
    float* s_gh = s_h + DD;
    int key = blockIdx.y, b = blockIdx.x, g = threadIdx.x;
    for (int i = g; i < DD * GG; i += GG) s_w[i] = g_wT[WHH_V + key * (DD * GG) + i];
    if (g < DD) s_h[g] = 0.f;
    __syncthreads();
    float bb = bhh[key * GG + g];
    for (int t = 0; t < 16; t++) {
        float acc = bb;
#pragma unroll 4
        for (int d = 0; d < DD; d++) acc += s_w[d * GG + g] * s_h[d];
        s_gh[g] = acc;
        __syncthreads();
        if (g < DD) {
            const float* xg = &g_vxg[((key * 16 + b) * 16 + t) * GG];
            float r = sigf(xg[g] + s_gh[g]);
            float z = sigf(xg[DD + g] + s_gh[DD + g]);
            float nn = tanhf(xg[2 * DD + g] + r * s_gh[2 * DD + g]);
            s_h[g] = (1.f - z) * nn + z * s_h[g];
        }
        __syncthreads();
    }
    if (g < DD) g_hv[(key * 16 + b) * DD + g] = s_h[g];
}

// ---------------- K7: ReLU + final FC --------------------------------------------
__global__ void k_fc(const float* fcw, const float* fcb, float* out) {
    __shared__ float pe[7 * DD];
    int b = blockIdx.x, o = threadIdx.x;
    for (int i = o; i < 7 * DD; i += 256) {
        int k = i / DD, d = i % DD;
        pe[i] = fmaxf(g_hv[(k * 16 + b) * DD + d], 0.f);
    }
    __syncthreads();
    if (o < NOUT) {
        float acc = fcb[o];
        for (int j = 0; j < 7 * DD; j++) acc += pe[j] * fcw[j * NOUT + o];
        out[b * NOUT + o] = acc;
    }
}

// ---------------- launch -----------------------------------------------------------
extern "C" void kernel_launch(void* const* d_in, const int* in_sizes, int n_in,
                              void* d_out, int out_size) {
    const int* tok_cond      = (const int*)d_in[0];
    const int* tok_proc      = (const int*)d_in[1];
    const int* tok_drug      = (const int*)d_in[2];
    const int* tok_lab_item  = (const int*)d_in[3];
    const int* tok_lab_value = (const int*)d_in[4];
    const int* tok_inj_item  = (const int*)d_in[5];
    const int* tok_inj_value = (const int*)d_in[6];
    const float* weight      = (const float*)d_in[7];
    const float* age         = (const float*)d_in[8];
    const float* emb_cond    = (const float*)d_in[9];
    const float* emb_proc    = (const float*)d_in[10];
    const float* emb_drug    = (const float*)d_in[11];
    const float* emb_li      = (const float*)d_in[12];
    const float* emb_lv      = (const float*)d_in[13];
    const float* emb_ii      = (const float*)d_in[14];
    const float* emb_iv      = (const float*)d_in[15];
    const float* mgru_wih    = (const float*)d_in[16];
    const float* mgru_whh    = (const float*)d_in[17];
    const float* mgru_bih    = (const float*)d_in[18];
    const float* mgru_bhh    = (const float*)d_in[19];
    const float* vgru_wih    = (const float*)d_in[20];
    const float* vgru_whh    = (const float*)d_in[21];
    const float* vgru_bih    = (const float*)d_in[22];
    const float* vgru_bhh    = (const float*)d_in[23];
    const float* info_w      = (const float*)d_in[24];
    const float* info_b      = (const float*)d_in[25];
    const float* fc_w        = (const float*)d_in[26];
    const float* fc_b        = (const float*)d_in[27];
    float* out = (float*)d_out;

    cudaFuncSetAttribute(k_mon_gru, cudaFuncAttributeMaxDynamicSharedMemorySize, 221184);
    cudaFuncSetAttribute(k_vis_gru, cudaFuncAttributeMaxDynamicSharedMemorySize, 198656);

    k_transpose<<<dim3(384, 24), 128>>>(mgru_wih, mgru_whh, vgru_wih, vgru_whh);
    k_embed_visit<<<dim3(256, 3), 128>>>(tok_cond, tok_proc, tok_drug,
                                         emb_cond, emb_proc, emb_drug);
    k_embed_mon<<<dim3(2048, 2), 128>>>(tok_lab_item, tok_lab_value,
                                        tok_inj_item, tok_inj_value,
                                        emb_li, emb_lv, emb_ii, emb_iv);
    k_xg34<<<dim3(256, 2), 384>>>(mgru_bih);
    k_xg012<<<dim3(256, 3), 384>>>(mgru_bih);
    k_mon_gru<<<dim3(29, 5), 384, 221184>>>(mgru_whh, mgru_bhh);
    k_vxg<<<dim3(16, 7), 384>>>(weight, age, info_w, info_b, vgru_bih);
    k_vis_gru<<<dim3(16, 7), 384, 198656>>>(vgru_bhh);
    k_fc<<<16, 256>>>(fc_w, fc_b, out);
}